// round 15
// baseline (speedup 1.0000x reference)
#include <cuda_runtime.h>

#define B  8
#define D  512
#define T  8192
#define CS 16
#define TC 512   // T / CS
#define DH 64    // D / 8

// Scratch (no cudaMalloc allowed)
__device__ float g_pooled[B * D * TC];          // 8 MiB
__device__ float g_hpart[4][B * DH * TC];       // 1 MiB per split-K slice

// readiness counters: (b*4 + dblock128) -> pooled rows done (target 128)
__device__ int g_cntA[32];

__global__ void reset_kernel() {
    int i = threadIdx.x;
    if (i < 32) g_cntA[i] = 0;
}

// ---------------------------------------------------------------------------
// Kernel 1 (MERGED): pool (bid < 4096) + gemm1 tail (bid >= 4096).
// Pool CTAs: one (b,d) row each — chunk sums, scan, write pooled, release.
// Gemm1 CTAs: scheduled last by the HW (grid tail), spin briefly on their
// 128-row counter, then do the split-K GEMM1 slice. This overlaps gemm1
// with pool's drain and removes one kernel-launch gap.
// ---------------------------------------------------------------------------
__global__ void __launch_bounds__(512, 4) pool_gemm1_kernel(
        const float* __restrict__ x, const float* __restrict__ w1) {
    __shared__ float csum[TC];
    __shared__ float wsum[16];
    __shared__ __align__(16) float Ps[64 * 64];      // gemm branch: [d][t]
    __shared__ __align__(16) float Ws[64 * 65 + 4];  // gemm branch: [o][d]

    int bid = blockIdx.x;

    if (bid < B * D) {
        // ================= POOL branch =================
        int row = bid;                         // b*D + d
        const float4* xr = reinterpret_cast<const float4*>(x) + (size_t)row * (T / 4);
        int j = threadIdx.x;

        float4 f0 = xr[j];
        float4 f1 = xr[j + 512];
        float4 f2 = xr[j + 1024];
        float4 f3 = xr[j + 1536];

        float s0 = (f0.x + f0.y) + (f0.z + f0.w);
        float s1 = (f1.x + f1.y) + (f1.z + f1.w);
        float s2 = (f2.x + f2.y) + (f2.z + f2.w);
        float s3 = (f3.x + f3.y) + (f3.z + f3.w);

        s0 += __shfl_xor_sync(0xffffffffu, s0, 1);
        s0 += __shfl_xor_sync(0xffffffffu, s0, 2);
        s1 += __shfl_xor_sync(0xffffffffu, s1, 1);
        s1 += __shfl_xor_sync(0xffffffffu, s1, 2);
        s2 += __shfl_xor_sync(0xffffffffu, s2, 1);
        s2 += __shfl_xor_sync(0xffffffffu, s2, 2);
        s3 += __shfl_xor_sync(0xffffffffu, s3, 1);
        s3 += __shfl_xor_sync(0xffffffffu, s3, 2);

        if ((j & 3) == 0) {
            int c = j >> 2;
            csum[c +   0] = s0;
            csum[c + 128] = s1;
            csum[c + 256] = s2;
            csum[c + 384] = s3;
        }
        __syncthreads();

        int lane = j & 31, warp = j >> 5;
        float v = csum[j];
        #pragma unroll
        for (int off = 1; off < 32; off <<= 1) {
            float n = __shfl_up_sync(0xffffffffu, v, off);
            if (lane >= off) v += n;
        }
        if (lane == 31) wsum[warp] = v;
        __syncthreads();
        if (warp == 0) {
            float w = (lane < 16) ? wsum[lane] : 0.f;
            #pragma unroll
            for (int off = 1; off < 16; off <<= 1) {
                float n = __shfl_up_sync(0xffffffffu, w, off);
                if (lane >= off) w += n;
            }
            if (lane < 16) wsum[lane] = w;
        }
        __syncthreads();

        float prefix = (warp > 0) ? wsum[warp - 1] : 0.f;
        float total  = v + prefix;
        g_pooled[(size_t)row * TC + j] = total / (float)(CS * (j + 1));

        // release this row
        __threadfence();
        __syncthreads();
        if (j == 0) atomicAdd(&g_cntA[row >> 7], 1);

    } else {
        // ================= GEMM1 branch (grid tail) =================
        int idx = bid - B * D;                 // 0..255
        int t0 = (idx & 7) * 64;
        int ks = (idx >> 3) & 3;               // k-slice 0..3
        int k0 = ks * 128;
        int b  = idx >> 5;

        int tid = threadIdx.x;
        int tq = tid & 15;          // t quad -> t = tq*4..+3
        int og = tid >> 4;          // 0..31  -> o = og*2, og*2+1

        float acc[2][4];
        acc[0][0] = acc[0][1] = acc[0][2] = acc[0][3] = 0.f;
        acc[1][0] = acc[1][1] = acc[1][2] = acc[1][3] = 0.f;

        // prologue (independent): w1 chunk 0 — overlaps the spin
        #pragma unroll
        for (int i = tid; i < 64 * 64; i += 512) {
            int o = i >> 6, d = i & 63;
            Ws[o * 65 + d] = w1[o * D + k0 + d];
        }

        // acquire: wait for my 128 pooled rows
        if (tid == 0) {
            while (atomicAdd(&g_cntA[b * 4 + ks], 0) < 128) __nanosleep(64);
            __threadfence();
        }
        __syncthreads();

        for (int c = 0; c < 2; c++) {
            int kc = k0 + c * 64;
            if (c == 1) {
                #pragma unroll
                for (int i = tid; i < 64 * 64; i += 512) {
                    int o = i >> 6, d = i & 63;
                    Ws[o * 65 + d] = w1[o * D + kc + d];
                }
            }
            #pragma unroll
            for (int i = tid; i < 64 * 16; i += 512) {
                int d = i >> 4, t4 = i & 15;
                *reinterpret_cast<float4*>(&Ps[d * 64 + t4 * 4]) =
                    *reinterpret_cast<const float4*>(
                        &g_pooled[((size_t)(b * D) + kc + d) * TC + t0 + t4 * 4]);
            }
            __syncthreads();

            #pragma unroll 8
            for (int dd = 0; dd < 64; dd++) {
                float4 p = *reinterpret_cast<const float4*>(&Ps[dd * 64 + tq * 4]);
                float w0 = Ws[(og * 2 + 0) * 65 + dd];
                float w1v = Ws[(og * 2 + 1) * 65 + dd];
                acc[0][0] = fmaf(w0, p.x, acc[0][0]);
                acc[0][1] = fmaf(w0, p.y, acc[0][1]);
                acc[0][2] = fmaf(w0, p.z, acc[0][2]);
                acc[0][3] = fmaf(w0, p.w, acc[0][3]);
                acc[1][0] = fmaf(w1v, p.x, acc[1][0]);
                acc[1][1] = fmaf(w1v, p.y, acc[1][1]);
                acc[1][2] = fmaf(w1v, p.z, acc[1][2]);
                acc[1][3] = fmaf(w1v, p.w, acc[1][3]);
            }
            __syncthreads();
        }

        float* hp = g_hpart[ks];
        #pragma unroll
        for (int o = 0; o < 2; o++) {
            float4 v = make_float4(acc[o][0], acc[o][1], acc[o][2], acc[o][3]);
            *reinterpret_cast<float4*>(
                &hp[((size_t)(b * DH) + og * 2 + o) * TC + t0 + tq * 4]) = v;
        }
    }
}

// ---------------------------------------------------------------------------
// Kernel 2 (FUSED): gemm2 + sigmoid gate + out = gate * x.
// R12 winner config: grid (32, 8, 8) = 2048 CTAs (~1.7 waves), smem ~21 KiB.
// Plain stream-ordered launch (no early launch — R14 showed squatting hurts).
// ---------------------------------------------------------------------------
__global__ void __launch_bounds__(256) gate_scale_kernel(
        const float* __restrict__ w2,
        const float* __restrict__ b1,
        const float* __restrict__ b2,
        const float* __restrict__ x,
        float* __restrict__ out) {
    __shared__ __align__(16) float Hs[64 * 16];      // [k][t] then gate [o][t]
    __shared__ __align__(16) float Ws[64 * 65 + 4];  // [o][k] padded

    int tid = threadIdx.x;
    int t0 = blockIdx.x * 16;                 // pooled-chunk tile start
    int o0 = (7 - blockIdx.y) * 64;           // reversed d-tile
    int b  = (B - 1) - blockIdx.z;            // reversed batch
    int tq = tid & 3;                         // t quad: t = tq*4..+3
    int og = tid >> 2;                        // 0..63 -> one o row

    // ---- Phase A1: H = relu(sum hpart + b1) and W2 ----
    {
        int k = tid >> 2, t4 = tid & 3;
        size_t idx = ((size_t)(b * DH) + k) * TC + t0 + t4 * 4;
        float4 a0 = *reinterpret_cast<const float4*>(&g_hpart[0][idx]);
        float4 a1 = *reinterpret_cast<const float4*>(&g_hpart[1][idx]);
        float4 a2 = *reinterpret_cast<const float4*>(&g_hpart[2][idx]);
        float4 a3 = *reinterpret_cast<const float4*>(&g_hpart[3][idx]);
        float bb = b1[k];
        float4 hv;
        hv.x = fmaxf(a0.x + a1.x + a2.x + a3.x + bb, 0.f);
        hv.y = fmaxf(a0.y + a1.y + a2.y + a3.y + bb, 0.f);
        hv.z = fmaxf(a0.z + a1.z + a2.z + a3.z + bb, 0.f);
        hv.w = fmaxf(a0.w + a1.w + a2.w + a3.w + bb, 0.f);
        *reinterpret_cast<float4*>(&Hs[k * 16 + t4 * 4]) = hv;
    }
    #pragma unroll
    for (int i = tid; i < 64 * 64; i += 256) {
        int o = i >> 6, k = i & 63;
        Ws[o * 65 + k] = w2[(o0 + o) * DH + k];
    }
    __syncthreads();

    // ---- Phase A2: GEMM 64o x 16t, K=64; thread = 1o x 4t ----
    float a0 = 0.f, a1 = 0.f, a2 = 0.f, a3 = 0.f;
    #pragma unroll 8
    for (int k = 0; k < 64; k++) {
        float4 h = *reinterpret_cast<const float4*>(&Hs[k * 16 + tq * 4]);
        float w = Ws[og * 65 + k];
        a0 = fmaf(w, h.x, a0);
        a1 = fmaf(w, h.y, a1);
        a2 = fmaf(w, h.z, a2);
        a3 = fmaf(w, h.w, a3);
    }
    __syncthreads();   // Hs reads done; reuse as gate

    // ---- Phase A3: sigmoid -> gate tile [o_local][16 t] ----
    {
        float bb = b2[o0 + og];
        float4 g;
        g.x = 1.f / (1.f + __expf(-(a0 + bb)));
        g.y = 1.f / (1.f + __expf(-(a1 + bb)));
        g.z = 1.f / (1.f + __expf(-(a2 + bb)));
        g.w = 1.f / (1.f + __expf(-(a3 + bb)));
        *reinterpret_cast<float4*>(&Hs[og * 16 + tq * 4]) = g;
    }
    __syncthreads();

    // ---- Phase B: out = gate * x over [64 d-rows][256 cols] ----
    int warp = tid >> 5, lane = tid & 31;
    int c0 = t0 * CS;

    #pragma unroll
    for (int r = 0; r < 8; r++) {
        int o_local = warp * 8 + r;
        size_t rowbase = ((size_t)(b * D) + o0 + o_local) * T + c0;
        const float4* xr = reinterpret_cast<const float4*>(x + rowbase);
        float4*       orp = reinterpret_cast<float4*>(out + rowbase);

        float4 x0 = xr[lane];
        float4 x1 = xr[lane + 32];
        float g0 = Hs[o_local * 16 + (lane >> 2)];
        float g1 = Hs[o_local * 16 + ((lane + 32) >> 2)];

        float4 v0 = make_float4(x0.x * g0, x0.y * g0, x0.z * g0, x0.w * g0);
        float4 v1 = make_float4(x1.x * g1, x1.y * g1, x1.z * g1, x1.w * g1);
        __stcs(&orp[lane], v0);
        __stcs(&orp[lane + 32], v1);
    }
}

// ---------------------------------------------------------------------------
extern "C" void kernel_launch(void* const* d_in, const int* in_sizes, int n_in,
                              void* d_out, int out_size) {
    const float* x  = (const float*)d_in[0];
    const float* w1 = (const float*)d_in[1];
    const float* b1 = (const float*)d_in[2];
    const float* w2 = (const float*)d_in[3];
    const float* b2 = (const float*)d_in[4];
    float* out = (float*)d_out;

    reset_kernel<<<1, 32>>>();
    pool_gemm1_kernel<<<B * D + 256, 512>>>(x, w1);
    gate_scale_kernel<<<dim3(32, 8, B), 256>>>(w2, b1, b2, x, out);
}

// round 16
// speedup vs baseline: 1.2186x; 1.2186x over previous
#include <cuda_runtime.h>

#define B  8
#define D  512
#define T  8192
#define CS 16
#define TC 512   // T / CS
#define DH 64    // D / 8

// Scratch (no cudaMalloc allowed)
__device__ float g_pooled[B * D * TC];          // 8 MiB
__device__ float g_hpart[4][B * DH * TC];       // 1 MiB per split-K slice

// ---------------------------------------------------------------------------
// Kernel 1: pool (unchanged from R13 best; ~23.7 us, DRAM ceiling).
// ---------------------------------------------------------------------------
__global__ void pool_kernel(const float* __restrict__ x) {
    int row = blockIdx.x;                      // b*D + d
    const float4* xr = reinterpret_cast<const float4*>(x) + (size_t)row * (T / 4);
    int j = threadIdx.x;

    __shared__ float csum[TC];
    __shared__ float wsum[16];

    float4 f0 = xr[j];
    float4 f1 = xr[j + 512];
    float4 f2 = xr[j + 1024];
    float4 f3 = xr[j + 1536];

    float s0 = (f0.x + f0.y) + (f0.z + f0.w);
    float s1 = (f1.x + f1.y) + (f1.z + f1.w);
    float s2 = (f2.x + f2.y) + (f2.z + f2.w);
    float s3 = (f3.x + f3.y) + (f3.z + f3.w);

    s0 += __shfl_xor_sync(0xffffffffu, s0, 1);
    s0 += __shfl_xor_sync(0xffffffffu, s0, 2);
    s1 += __shfl_xor_sync(0xffffffffu, s1, 1);
    s1 += __shfl_xor_sync(0xffffffffu, s1, 2);
    s2 += __shfl_xor_sync(0xffffffffu, s2, 1);
    s2 += __shfl_xor_sync(0xffffffffu, s2, 2);
    s3 += __shfl_xor_sync(0xffffffffu, s3, 1);
    s3 += __shfl_xor_sync(0xffffffffu, s3, 2);

    if ((j & 3) == 0) {
        int c = j >> 2;
        csum[c +   0] = s0;
        csum[c + 128] = s1;
        csum[c + 256] = s2;
        csum[c + 384] = s3;
    }
    __syncthreads();

    int lane = j & 31, warp = j >> 5;
    float v = csum[j];
    #pragma unroll
    for (int off = 1; off < 32; off <<= 1) {
        float n = __shfl_up_sync(0xffffffffu, v, off);
        if (lane >= off) v += n;
    }
    if (lane == 31) wsum[warp] = v;
    __syncthreads();
    if (warp == 0) {
        float w = (lane < 16) ? wsum[lane] : 0.f;
        #pragma unroll
        for (int off = 1; off < 16; off <<= 1) {
            float n = __shfl_up_sync(0xffffffffu, w, off);
            if (lane >= off) w += n;
        }
        if (lane < 16) wsum[lane] = w;
    }
    __syncthreads();

    float prefix = (warp > 0) ? wsum[warp - 1] : 0.f;
    float total  = v + prefix;
    g_pooled[(size_t)row * TC + j] = total / (float)(CS * (j + 1));

    cudaTriggerProgrammaticLaunchCompletion();
}

// ---------------------------------------------------------------------------
// Kernel 2a: GEMM1 split-K via tensor cores (mma.sync m16n8k8 tf32).
// grid (8 t-tiles, 4 k-slices, B) = 256 CTAs, 256 threads (8 warps).
// CTA tile: 64o x 64t, K=128 (full slice in smem). Warp w: m16 x n32.
// PDL: w1 slice loaded before grid sync (independent of pool).
// ---------------------------------------------------------------------------
__device__ __forceinline__ unsigned int f2tf32(float f) {
    unsigned int r;
    asm("cvt.rna.tf32.f32 %0, %1;" : "=r"(r) : "f"(f));
    return r;
}

__global__ void __launch_bounds__(256) gemm1_kernel(const float* __restrict__ w1) {
    __shared__ __align__(16) float Ws[64 * 132];   // [o][d] pad 132 (A, conflict-free)
    __shared__ __align__(16) float Ps[128 * 68];   // [d][t] pad 68  (B)

    int tid = threadIdx.x;
    int lane = tid & 31, warp = tid >> 5;
    int t0 = blockIdx.x * 64;
    int k0 = blockIdx.y * 128;
    int b  = blockIdx.z;
    int m0 = (warp & 3) * 16;       // o offset of this warp
    int n0 = (warp >> 2) * 32;      // t offset of this warp
    int g  = lane >> 2;             // groupID 0..7
    int tg = lane & 3;              // threadID_in_group 0..3

    // Independent prologue: full w1 slice [64 o][128 d]
    #pragma unroll
    for (int i = tid; i < 64 * 32; i += 256) {
        int o = i >> 5, d4 = i & 31;
        *reinterpret_cast<float4*>(&Ws[o * 132 + d4 * 4]) =
            *reinterpret_cast<const float4*>(&w1[o * D + k0 + d4 * 4]);
    }

    cudaGridDependencySynchronize();   // wait for pool's g_pooled

    // pooled slice [128 d][64 t]
    #pragma unroll
    for (int i = tid; i < 128 * 16; i += 256) {
        int d = i >> 4, t4 = i & 15;
        *reinterpret_cast<float4*>(&Ps[d * 68 + t4 * 4]) =
            *reinterpret_cast<const float4*>(
                &g_pooled[((size_t)(b * D) + k0 + d) * TC + t0 + t4 * 4]);
    }
    __syncthreads();

    float c[4][4];
    #pragma unroll
    for (int j = 0; j < 4; j++)
        #pragma unroll
        for (int q = 0; q < 4; q++) c[j][q] = 0.f;

    #pragma unroll
    for (int kk = 0; kk < 16; kk++) {
        int kb = kk * 8;
        // A fragment (w1): row-major m16 x k8
        unsigned int a0 = f2tf32(Ws[(m0 + g    ) * 132 + kb + tg    ]);
        unsigned int a1 = f2tf32(Ws[(m0 + g + 8) * 132 + kb + tg    ]);
        unsigned int a2 = f2tf32(Ws[(m0 + g    ) * 132 + kb + tg + 4]);
        unsigned int a3 = f2tf32(Ws[(m0 + g + 8) * 132 + kb + tg + 4]);

        #pragma unroll
        for (int j = 0; j < 4; j++) {
            int n = n0 + j * 8;
            // B fragment (pooled): col-major k8 x n8
            unsigned int b0 = f2tf32(Ps[(kb + tg    ) * 68 + n + g]);
            unsigned int b1 = f2tf32(Ps[(kb + tg + 4) * 68 + n + g]);
            asm volatile(
                "mma.sync.aligned.m16n8k8.row.col.f32.tf32.tf32.f32 "
                "{%0,%1,%2,%3}, {%4,%5,%6,%7}, {%8,%9}, {%0,%1,%2,%3};"
                : "+f"(c[j][0]), "+f"(c[j][1]), "+f"(c[j][2]), "+f"(c[j][3])
                : "r"(a0), "r"(a1), "r"(a2), "r"(a3), "r"(b0), "r"(b1));
        }
    }

    // Epilogue: D fragment -> hpart.  c0:(g, tg*2) c1:(g, tg*2+1)
    //                                 c2:(g+8, tg*2) c3:(g+8, tg*2+1)
    float* hp = g_hpart[blockIdx.y];
    size_t rowA = ((size_t)(b * DH) + m0 + g    ) * TC + t0;
    size_t rowB = ((size_t)(b * DH) + m0 + g + 8) * TC + t0;
    #pragma unroll
    for (int j = 0; j < 4; j++) {
        int col = n0 + j * 8 + tg * 2;
        *reinterpret_cast<float2*>(&hp[rowA + col]) = make_float2(c[j][0], c[j][1]);
        *reinterpret_cast<float2*>(&hp[rowB + col]) = make_float2(c[j][2], c[j][3]);
    }

    cudaTriggerProgrammaticLaunchCompletion();
}

// ---------------------------------------------------------------------------
// Kernel 2b (FUSED): gemm2 + sigmoid gate + out = gate * x.
// Unchanged R12/R13 winner: grid (32,8,8) = 2048 CTAs (~1.7 waves).
// PDL: W2 prologue only, then grid sync.
// ---------------------------------------------------------------------------
__global__ void __launch_bounds__(256) gate_scale_kernel(
        const float* __restrict__ w2,
        const float* __restrict__ b1,
        const float* __restrict__ b2,
        const float* __restrict__ x,
        float* __restrict__ out) {
    __shared__ __align__(16) float Hs[64 * 16];      // [k][t] then gate [o][t]
    __shared__ __align__(16) float Ws[64 * 65 + 4];  // [o][k] padded

    int tid = threadIdx.x;
    int t0 = blockIdx.x * 16;                 // pooled-chunk tile start
    int o0 = (7 - blockIdx.y) * 64;           // reversed d-tile
    int b  = (B - 1) - blockIdx.z;            // reversed batch
    int tq = tid & 3;                         // t quad: t = tq*4..+3
    int og = tid >> 2;                        // 0..63 -> one o row

    // Independent prologue: W2
    #pragma unroll
    for (int i = tid; i < 64 * 64; i += 256) {
        int o = i >> 6, k = i & 63;
        Ws[o * 65 + k] = w2[(o0 + o) * DH + k];
    }

    cudaGridDependencySynchronize();

    // ---- Phase A1: H = relu(sum hpart + b1) ----
    {
        int k = tid >> 2, t4 = tid & 3;
        size_t idx = ((size_t)(b * DH) + k) * TC + t0 + t4 * 4;
        float4 a0 = *reinterpret_cast<const float4*>(&g_hpart[0][idx]);
        float4 a1 = *reinterpret_cast<const float4*>(&g_hpart[1][idx]);
        float4 a2 = *reinterpret_cast<const float4*>(&g_hpart[2][idx]);
        float4 a3 = *reinterpret_cast<const float4*>(&g_hpart[3][idx]);
        float bb = b1[k];
        float4 hv;
        hv.x = fmaxf(a0.x + a1.x + a2.x + a3.x + bb, 0.f);
        hv.y = fmaxf(a0.y + a1.y + a2.y + a3.y + bb, 0.f);
        hv.z = fmaxf(a0.z + a1.z + a2.z + a3.z + bb, 0.f);
        hv.w = fmaxf(a0.w + a1.w + a2.w + a3.w + bb, 0.f);
        *reinterpret_cast<float4*>(&Hs[k * 16 + t4 * 4]) = hv;
    }
    __syncthreads();

    // ---- Phase A2: GEMM 64o x 16t, K=64; thread = 1o x 4t ----
    float a0 = 0.f, a1 = 0.f, a2 = 0.f, a3 = 0.f;
    #pragma unroll 8
    for (int k = 0; k < 64; k++) {
        float4 h = *reinterpret_cast<const float4*>(&Hs[k * 16 + tq * 4]);
        float w = Ws[og * 65 + k];
        a0 = fmaf(w, h.x, a0);
        a1 = fmaf(w, h.y, a1);
        a2 = fmaf(w, h.z, a2);
        a3 = fmaf(w, h.w, a3);
    }
    __syncthreads();   // Hs reads done; reuse as gate

    // ---- Phase A3: sigmoid -> gate tile [o_local][16 t] ----
    {
        float bb = b2[o0 + og];
        float4 g;
        g.x = 1.f / (1.f + __expf(-(a0 + bb)));
        g.y = 1.f / (1.f + __expf(-(a1 + bb)));
        g.z = 1.f / (1.f + __expf(-(a2 + bb)));
        g.w = 1.f / (1.f + __expf(-(a3 + bb)));
        *reinterpret_cast<float4*>(&Hs[og * 16 + tq * 4]) = g;
    }
    __syncthreads();

    // ---- Phase B: out = gate * x over [64 d-rows][256 cols] ----
    int warp = tid >> 5, lane = tid & 31;
    int c0 = t0 * CS;

    #pragma unroll
    for (int r = 0; r < 8; r++) {
        int o_local = warp * 8 + r;
        size_t rowbase = ((size_t)(b * D) + o0 + o_local) * T + c0;
        const float4* xr = reinterpret_cast<const float4*>(x + rowbase);
        float4*       orp = reinterpret_cast<float4*>(out + rowbase);

        float4 x0 = xr[lane];
        float4 x1 = xr[lane + 32];
        float g0 = Hs[o_local * 16 + (lane >> 2)];
        float g1 = Hs[o_local * 16 + ((lane + 32) >> 2)];

        float4 v0 = make_float4(x0.x * g0, x0.y * g0, x0.z * g0, x0.w * g0);
        float4 v1 = make_float4(x1.x * g1, x1.y * g1, x1.z * g1, x1.w * g1);
        __stcs(&orp[lane], v0);
        __stcs(&orp[lane + 32], v1);
    }
}

// ---------------------------------------------------------------------------
extern "C" void kernel_launch(void* const* d_in, const int* in_sizes, int n_in,
                              void* d_out, int out_size) {
    const float* x  = (const float*)d_in[0];
    const float* w1 = (const float*)d_in[1];
    const float* b1 = (const float*)d_in[2];
    const float* w2 = (const float*)d_in[3];
    const float* b2 = (const float*)d_in[4];
    float* out = (float*)d_out;

    pool_kernel<<<B * D, 512>>>(x);

    cudaLaunchAttribute attrs[1];
    attrs[0].id = cudaLaunchAttributeProgrammaticStreamSerialization;
    attrs[0].val.programmaticStreamSerializationAllowed = 1;

    {
        cudaLaunchConfig_t cfg = {};
        cfg.gridDim  = dim3(8, 4, B);
        cfg.blockDim = dim3(256, 1, 1);
        cfg.attrs = attrs;
        cfg.numAttrs = 1;
        cfg.stream = 0;
        cudaLaunchKernelEx(&cfg, gemm1_kernel, w1);
    }
    {
        cudaLaunchConfig_t cfg = {};
        cfg.gridDim  = dim3(32, 8, B);
        cfg.blockDim = dim3(256, 1, 1);
        cfg.attrs = attrs;
        cfg.numAttrs = 1;
        cfg.stream = 0;
        cudaLaunchKernelEx(&cfg, gate_scale_kernel, w2, b1, b2, x, out);
    }
}